// round 3
// baseline (speedup 1.0000x reference)
#include <cuda_runtime.h>
#include <cuda_bf16.h>

#define N_NODES 50000
#define N_EDGES 800000
#define LATENT 32
#define STEPS 10
#define NEG_SLOPE 0.01f
#define LN_EPS 1e-5f

#define SCAN_CHUNK 1024
#define N_CHUNKS ((N_NODES + SCAN_CHUNK - 1) / SCAN_CHUNK)   // 49

// ---------------- scratch (device globals; no allocation allowed) ----------------
__device__ float g_h[N_NODES * LATENT];       // node latent
__device__ float g_e[N_EDGES * LATENT];       // edge latent, RECEIVER-SORTED order
__device__ float g_hs[N_NODES * LATENT];      // h @ W_src  (per step)
__device__ float g_hd[N_NODES * LATENT];      // h @ W_dst  (per step)
__device__ float g_inv[N_NODES];              // 1/max(indeg,1)

__device__ int g_hist[N_NODES];               // in-degree histogram
__device__ int g_off[N_NODES + 1];            // CSR offsets (sorted-edge ranges)
__device__ int g_cursor[N_NODES];             // scatter cursors
__device__ int g_csum[N_CHUNKS];              // chunk sums for scan
__device__ int g_eid[N_EDGES];                // sorted pos -> original edge id
__device__ int g_snd_s[N_EDGES];              // sender per sorted edge
__device__ int g_rcv_s[N_EDGES];              // receiver per sorted edge

__device__ __forceinline__ float leaky(float v) {
    return v >= 0.f ? v : NEG_SLOPE * v;
}

__device__ __forceinline__ float warp_sum(float v) {
    v += __shfl_xor_sync(0xffffffffu, v, 16);
    v += __shfl_xor_sync(0xffffffffu, v, 8);
    v += __shfl_xor_sync(0xffffffffu, v, 4);
    v += __shfl_xor_sync(0xffffffffu, v, 2);
    v += __shfl_xor_sync(0xffffffffu, v, 1);
    return v;
}

// ================= one-time preprocessing: counting sort by receiver =================
__global__ void zero_hist() {
    int i = blockIdx.x * blockDim.x + threadIdx.x;
    if (i < N_NODES) g_hist[i] = 0;
}

__global__ void hist_edges(const int* __restrict__ rcv) {
    int i = blockIdx.x * blockDim.x + threadIdx.x;
    if (i < N_EDGES) atomicAdd(&g_hist[rcv[i]], 1);
}

__global__ void scan_chunks() {
    __shared__ int sh[SCAN_CHUNK];
    int i = blockIdx.x * SCAN_CHUNK + threadIdx.x;
    int v = (i < N_NODES) ? g_hist[i] : 0;
    sh[threadIdx.x] = v;
    __syncthreads();
#pragma unroll
    for (int d = 1; d < SCAN_CHUNK; d <<= 1) {
        int t = (threadIdx.x >= d) ? sh[threadIdx.x - d] : 0;
        __syncthreads();
        sh[threadIdx.x] += t;
        __syncthreads();
    }
    if (i < N_NODES) g_off[i] = sh[threadIdx.x] - v;     // chunk-local exclusive
    if (threadIdx.x == SCAN_CHUNK - 1) g_csum[blockIdx.x] = sh[threadIdx.x];
}

__global__ void scan_sums() {
    int acc = 0;
    for (int c = 0; c < N_CHUNKS; c++) { int t = g_csum[c]; g_csum[c] = acc; acc += t; }
    g_off[N_NODES] = acc;   // == N_EDGES
}

__global__ void add_offsets() {
    int i = blockIdx.x * blockDim.x + threadIdx.x;
    if (i < N_NODES) {
        int o = g_off[i] + g_csum[i / SCAN_CHUNK];
        g_off[i] = o;
        g_cursor[i] = o;
        g_inv[i] = 1.f / fmaxf((float)g_hist[i], 1.f);
    }
}

__global__ void scatter_edges(const int* __restrict__ snd, const int* __restrict__ rcv) {
    int i = blockIdx.x * blockDim.x + threadIdx.x;
    if (i < N_EDGES) {
        int r = rcv[i];
        int pos = atomicAdd(&g_cursor[r], 1);
        g_eid[pos] = i;
        g_snd_s[pos] = snd[i];
        g_rcv_s[pos] = r;
    }
}

// ================= encoders =================
__global__ void encode_nodes(const float* __restrict__ x,
                             const float* __restrict__ W,
                             const float* __restrict__ b) {
    int i = blockIdx.x * blockDim.x + threadIdx.x;
    if (i >= N_NODES * 32) return;
    int n = i >> 5, c = i & 31;
    float a = b[c];
#pragma unroll
    for (int k = 0; k < 6; k++) a += x[n * 6 + k] * W[k * 32 + c];
    g_h[i] = leaky(a);
}

// edge latent written in receiver-sorted order
__global__ void encode_edges(const float* __restrict__ ea,
                             const float* __restrict__ W,
                             const float* __restrict__ b) {
    int i = blockIdx.x * blockDim.x + threadIdx.x;
    if (i >= N_EDGES * 32) return;
    int e = i >> 5, c = i & 31;
    int eid = g_eid[e];
    float a = b[c];
#pragma unroll
    for (int k = 0; k < 3; k++) a += ea[eid * 3 + k] * W[k * 32 + c];
    g_e[i] = leaky(a);
}

// ================= per-step: Hs = h@W[32:64], Hd = h@W[64:96] =================
__global__ void node_pre(const float* __restrict__ eW) {
    __shared__ float ws[64 * 32];
    for (int i = threadIdx.x; i < 64 * 32; i += blockDim.x)
        ws[i] = eW[32 * 32 + i];
    __syncthreads();
    int lane = threadIdx.x & 31;
    int warp = (blockIdx.x * blockDim.x + threadIdx.x) >> 5;
    int nwarps = (gridDim.x * blockDim.x) >> 5;
    for (int n = warp; n < N_NODES; n += nwarps) {
        float hv = g_h[n * 32 + lane];
        float aS = 0.f, aD = 0.f;
#pragma unroll
        for (int k = 0; k < 32; k++) {
            float hk = __shfl_sync(0xffffffffu, hv, k);
            aS += hk * ws[k * 32 + lane];
            aD += hk * ws[(32 + k) * 32 + lane];
        }
        g_hs[n * 32 + lane] = aS;
        g_hd[n * 32 + lane] = aD;
    }
}

// ================= per-step: edge update (no atomics) =================
__global__ void __launch_bounds__(256) edge_update(
        const float* __restrict__ eW, const float* __restrict__ eb,
        const float* __restrict__ lns, const float* __restrict__ lnb) {
    int lane = threadIdx.x & 31;
    int warp = (blockIdx.x * blockDim.x + threadIdx.x) >> 5;
    int nwarps = (gridDim.x * blockDim.x) >> 5;

    float w[32];
#pragma unroll
    for (int k = 0; k < 32; k++) w[k] = eW[k * 32 + lane];
    float bias = eb[lane], sc = lns[lane], bi = lnb[lane];

    for (int e = warp; e < N_EDGES; e += nwarps) {
        float ev = g_e[e * 32 + lane];
        int s = g_snd_s[e], r = g_rcv_s[e];
        float acc0 = bias + __ldg(&g_hs[s * 32 + lane]);
        float acc1 = __ldg(&g_hd[r * 32 + lane]);
        float acc2 = 0.f, acc3 = 0.f;
#pragma unroll
        for (int k = 0; k < 32; k += 4) {
            acc0 += __shfl_sync(0xffffffffu, ev, k + 0) * w[k + 0];
            acc1 += __shfl_sync(0xffffffffu, ev, k + 1) * w[k + 1];
            acc2 += __shfl_sync(0xffffffffu, ev, k + 2) * w[k + 2];
            acc3 += __shfl_sync(0xffffffffu, ev, k + 3) * w[k + 3];
        }
        float m = leaky((acc0 + acc1) + (acc2 + acc3));
        float mu = warp_sum(m) * (1.f / 32.f);
        float d = m - mu;
        float var = warp_sum(d * d) * (1.f / 32.f);
        float y = d * rsqrtf(var + LN_EPS) * sc + bi;
        g_e[e * 32 + lane] = ev + y;
    }
}

// ================= per-step: node update with fused contiguous aggregation =================
__global__ void __launch_bounds__(256) node_update(
        const float* __restrict__ nW, const float* __restrict__ nb,
        const float* __restrict__ lns, const float* __restrict__ lnb) {
    __shared__ float ws[64 * 32];
    for (int i = threadIdx.x; i < 64 * 32; i += blockDim.x) ws[i] = nW[i];
    __syncthreads();
    int lane = threadIdx.x & 31;
    int warp = (blockIdx.x * blockDim.x + threadIdx.x) >> 5;
    int nwarps = (gridDim.x * blockDim.x) >> 5;
    float bias = nb[lane], sc = lns[lane], bi = lnb[lane];
    for (int n = warp; n < N_NODES; n += nwarps) {
        int beg = g_off[n], end = g_off[n + 1];
        // contiguous segmented sum over this node's in-edges (4-way MLP)
        float s0 = 0.f, s1 = 0.f, s2 = 0.f, s3 = 0.f;
        int j = beg;
        for (; j + 3 < end; j += 4) {
            s0 += g_e[(j + 0) * 32 + lane];
            s1 += g_e[(j + 1) * 32 + lane];
            s2 += g_e[(j + 2) * 32 + lane];
            s3 += g_e[(j + 3) * 32 + lane];
        }
        for (; j < end; j++) s0 += g_e[j * 32 + lane];
        float av = ((s0 + s1) + (s2 + s3)) * g_inv[n];

        float hv = g_h[n * 32 + lane];
        float acc = bias;
#pragma unroll
        for (int k = 0; k < 32; k++) {
            float a = __shfl_sync(0xffffffffu, hv, k);
            float b2 = __shfl_sync(0xffffffffu, av, k);
            acc += a * ws[k * 32 + lane] + b2 * ws[(32 + k) * 32 + lane];
        }
        float m = leaky(acc);
        float mu = warp_sum(m) * (1.f / 32.f);
        float d = m - mu;
        float var = warp_sum(d * d) * (1.f / 32.f);
        float y = d * rsqrtf(var + LN_EPS) * sc + bi;
        g_h[n * 32 + lane] = hv + y;
    }
}

// ================= decoder =================
__global__ void decode(const float* __restrict__ W1, const float* __restrict__ b1,
                       const float* __restrict__ W2, const float* __restrict__ b2,
                       float* __restrict__ out) {
    __shared__ float ws[32 * 32];
    for (int i = threadIdx.x; i < 32 * 32; i += blockDim.x) ws[i] = W1[i];
    __syncthreads();
    int lane = threadIdx.x & 31;
    int warp = (blockIdx.x * blockDim.x + threadIdx.x) >> 5;
    int nwarps = (gridDim.x * blockDim.x) >> 5;
    for (int n = warp; n < N_NODES; n += nwarps) {
        float hv = g_h[n * 32 + lane];
        float t = b1[lane];
#pragma unroll
        for (int k = 0; k < 32; k++)
            t += __shfl_sync(0xffffffffu, hv, k) * ws[k * 32 + lane];
        t = leaky(t);
        float r = warp_sum(t * W2[lane]);
        if (lane == 0) out[n] = r + b2[0];
    }
}

// ================= launch =================
extern "C" void kernel_launch(void* const* d_in, const int* in_sizes, int n_in,
                              void* d_out, int out_size) {
    const float* x   = (const float*)d_in[0];
    const float* ea  = (const float*)d_in[1];
    const int*   snd = (const int*)d_in[2];
    const int*   rcv = (const int*)d_in[3];
    const float* neW = (const float*)d_in[4];
    const float* neb = (const float*)d_in[5];
    const float* eeW = (const float*)d_in[6];
    const float* eeb = (const float*)d_in[7];
    const float* eW  = (const float*)d_in[8];
    const float* eb  = (const float*)d_in[9];
    const float* els = (const float*)d_in[10];
    const float* elb = (const float*)d_in[11];
    const float* nW  = (const float*)d_in[12];
    const float* nb  = (const float*)d_in[13];
    const float* nls = (const float*)d_in[14];
    const float* nlb = (const float*)d_in[15];
    const float* dW1 = (const float*)d_in[16];
    const float* db1 = (const float*)d_in[17];
    const float* dW2 = (const float*)d_in[18];
    const float* db2 = (const float*)d_in[19];
    float* out = (float*)d_out;

    // one-time: counting sort of edges by receiver
    zero_hist<<<(N_NODES + 255) / 256, 256>>>();
    hist_edges<<<(N_EDGES + 255) / 256, 256>>>(rcv);
    scan_chunks<<<N_CHUNKS, SCAN_CHUNK>>>();
    scan_sums<<<1, 1>>>();
    add_offsets<<<(N_NODES + 255) / 256, 256>>>();
    scatter_edges<<<(N_EDGES + 255) / 256, 256>>>(snd, rcv);

    encode_nodes<<<(N_NODES * 32 + 255) / 256, 256>>>(x, neW, neb);
    encode_edges<<<(N_EDGES * 32 + 255) / 256, 256>>>(ea, eeW, eeb);

    for (int s = 0; s < STEPS; s++) {
        node_pre<<<592, 256>>>(eW + s * 96 * 32);
        edge_update<<<1480, 256>>>(eW + s * 96 * 32, eb + s * 32,
                                   els + s * 32, elb + s * 32);
        node_update<<<592, 256>>>(nW + s * 64 * 32, nb + s * 32,
                                  nls + s * 32, nlb + s * 32);
    }
    decode<<<592, 256>>>(dW1, db1, dW2, db2, out);
}

// round 4
// speedup vs baseline: 1.6336x; 1.6336x over previous
#include <cuda_runtime.h>
#include <cuda_bf16.h>

#define N_NODES 50000
#define N_EDGES 800000
#define STEPS 10
#define NEG_SLOPE 0.01f
#define LN_EPS 1e-5f

#define ENC_EDGE_BLOCKS 3125              // 3125*256 = 800000
#define ENC_NODE_BLOCKS 1184
#define EDGE_BLOCKS 888                   // 6 blocks/SM * 148
#define NODE_BLOCKS 592

// ---------------- device scratch (no allocation allowed) ----------------
__device__ float g_h [N_NODES * 32];
__device__ float g_e [N_EDGES * 32];      // receiver-sorted
__device__ float g_hs[N_NODES * 32];
__device__ float g_hd[N_NODES * 32];
__device__ float g_inv[N_NODES];
__device__ int   g_hist[N_NODES];         // zero-init; re-zeroed inside fused_encode each replay
__device__ int   g_off [N_NODES + 1];
__device__ int   g_cursor[N_NODES];
__device__ int   g_snd_s[N_EDGES];
__device__ int   g_rcv_s[N_EDGES];

__device__ __forceinline__ float leaky(float v) {
    return v >= 0.f ? v : NEG_SLOPE * v;
}

// ================= launch 1: in-degree histogram =================
__global__ void hist_edges(const int* __restrict__ rcv) {
    int i = blockIdx.x * blockDim.x + threadIdx.x;
    if (i < N_EDGES) atomicAdd(&g_hist[rcv[i]], 1);
}

// ================= launch 2: single-block full scan -> off/cursor/inv =================
__global__ void scan_all() {
    __shared__ int sh[1024];
    int tid = threadIdx.x;
    int base = 0;
    const int nchunks = (N_NODES + 1023) / 1024;
    for (int c = 0; c < nchunks; c++) {
        __syncthreads();
        int i = c * 1024 + tid;
        int v = (i < N_NODES) ? g_hist[i] : 0;
        sh[tid] = v;
        __syncthreads();
#pragma unroll
        for (int d = 1; d < 1024; d <<= 1) {
            int t = (tid >= d) ? sh[tid - d] : 0;
            __syncthreads();
            sh[tid] += t;
            __syncthreads();
        }
        if (i < N_NODES) {
            int off = base + sh[tid] - v;
            g_off[i] = off;
            g_cursor[i] = off;
            g_inv[i] = 1.f / fmaxf((float)v, 1.f);
        }
        base += sh[1023];
    }
    if (tid == 0) g_off[N_NODES] = base;   // == N_EDGES
}

// ================= launch 3: fused scatter + edge-encode + node-encode + node_pre(step0) ====
__global__ void __launch_bounds__(256) fused_encode(
        const float* __restrict__ ea, const int* __restrict__ snd, const int* __restrict__ rcv,
        const float* __restrict__ eeW, const float* __restrict__ eeb,
        const float* __restrict__ x, const float* __restrict__ neW, const float* __restrict__ neb,
        const float* __restrict__ eW0) {
    __shared__ float sw[64 * 32];
    __shared__ float sw2[224];

    if (blockIdx.x < ENC_EDGE_BLOCKS) {
        // ---- edge blocks: counting-sort scatter + encode into sorted slot ----
        if (threadIdx.x < 96) sw[threadIdx.x] = eeW[threadIdx.x];
        else if (threadIdx.x < 128) sw[threadIdx.x] = eeb[threadIdx.x - 96];
        __syncthreads();
        int i = blockIdx.x * 256 + threadIdx.x;
        if (i < N_EDGES) {
            int r = rcv[i], s = snd[i];
            int pos = atomicAdd(&g_cursor[r], 1);
            g_snd_s[pos] = s;
            g_rcv_s[pos] = r;
            float a0 = ea[i * 3 + 0], a1 = ea[i * 3 + 1], a2 = ea[i * 3 + 2];
            float4* dst = (float4*)&g_e[pos * 32];
#pragma unroll
            for (int c4 = 0; c4 < 8; c4++) {
                float4 v;
                v.x = leaky(sw[96 + c4 * 4 + 0] + a0 * sw[0 * 32 + c4 * 4 + 0] + a1 * sw[1 * 32 + c4 * 4 + 0] + a2 * sw[2 * 32 + c4 * 4 + 0]);
                v.y = leaky(sw[96 + c4 * 4 + 1] + a0 * sw[0 * 32 + c4 * 4 + 1] + a1 * sw[1 * 32 + c4 * 4 + 1] + a2 * sw[2 * 32 + c4 * 4 + 1]);
                v.z = leaky(sw[96 + c4 * 4 + 2] + a0 * sw[0 * 32 + c4 * 4 + 2] + a1 * sw[1 * 32 + c4 * 4 + 2] + a2 * sw[2 * 32 + c4 * 4 + 2]);
                v.w = leaky(sw[96 + c4 * 4 + 3] + a0 * sw[0 * 32 + c4 * 4 + 3] + a1 * sw[1 * 32 + c4 * 4 + 3] + a2 * sw[2 * 32 + c4 * 4 + 3]);
                dst[c4] = v;
            }
        }
    } else {
        // ---- node blocks: encode h + Hs/Hd for step 0 + re-zero hist for next replay ----
        for (int i = threadIdx.x; i < 2048; i += 256) sw[i] = eW0[32 * 32 + i];
        for (int i = threadIdx.x; i < 224; i += 256)
            sw2[i] = (i < 192) ? neW[i] : neb[i - 192];
        __syncthreads();
        int lane = threadIdx.x & 31;
        int nb = blockIdx.x - ENC_EDGE_BLOCKS;
        int warp = nb * 8 + (threadIdx.x >> 5);
        int nwarps = ENC_NODE_BLOCKS * 8;
        for (int n = warp; n < N_NODES; n += nwarps) {
            float a = sw2[192 + lane];
#pragma unroll
            for (int k = 0; k < 6; k++) a += x[n * 6 + k] * sw2[k * 32 + lane];
            float hv = leaky(a);
            g_h[n * 32 + lane] = hv;
            float aS = 0.f, aD = 0.f;
#pragma unroll
            for (int k = 0; k < 32; k++) {
                float t = __shfl_sync(0xffffffffu, hv, k);
                aS += t * sw[k * 32 + lane];
                aD += t * sw[(32 + k) * 32 + lane];
            }
            g_hs[n * 32 + lane] = aS;
            g_hd[n * 32 + lane] = aD;
        }
        // zero histogram for the next replay (consumed already by scan_all)
        int gtid = nb * 256 + threadIdx.x;
        for (int i = gtid; i < N_NODES; i += ENC_NODE_BLOCKS * 256) g_hist[i] = 0;
    }
}

// ================= per-step: edge update (2-edge ILP, smem W, 1-pass LN) =================
__global__ void __launch_bounds__(256) edge_update(
        const float* __restrict__ eW, const float* __restrict__ eb,
        const float* __restrict__ lns, const float* __restrict__ lnb) {
    __shared__ float ws[32 * 32];
    __shared__ float prm[96];
    for (int i = threadIdx.x; i < 1024; i += 256) ws[i] = eW[i];
    if (threadIdx.x < 32) {
        prm[threadIdx.x] = eb[threadIdx.x];
        prm[32 + threadIdx.x] = lns[threadIdx.x];
        prm[64 + threadIdx.x] = lnb[threadIdx.x];
    }
    __syncthreads();
    int lane = threadIdx.x & 31;
    int warp = (blockIdx.x * blockDim.x + threadIdx.x) >> 5;
    int nwarps = (gridDim.x * blockDim.x) >> 5;
    float bias = prm[lane], sc = prm[32 + lane], bi = prm[64 + lane];

    const int npairs = N_EDGES / 2;
    for (int p = warp; p < npairs; p += nwarps) {
        int e0 = 2 * p, e1 = 2 * p + 1;
        float ev0 = g_e[e0 * 32 + lane];
        float ev1 = g_e[e1 * 32 + lane];
        int s0 = g_snd_s[e0], r0 = g_rcv_s[e0];
        int s1 = g_snd_s[e1], r1 = g_rcv_s[e1];
        float a0 = bias + g_hs[s0 * 32 + lane] + g_hd[r0 * 32 + lane];
        float a1 = bias + g_hs[s1 * 32 + lane] + g_hd[r1 * 32 + lane];
        float b0 = 0.f, b1 = 0.f;
#pragma unroll
        for (int k = 0; k < 32; k += 2) {
            float wk0 = ws[k * 32 + lane];
            float wk1 = ws[(k + 1) * 32 + lane];
            a0 += __shfl_sync(0xffffffffu, ev0, k) * wk0;
            b0 += __shfl_sync(0xffffffffu, ev0, k + 1) * wk1;
            a1 += __shfl_sync(0xffffffffu, ev1, k) * wk0;
            b1 += __shfl_sync(0xffffffffu, ev1, k + 1) * wk1;
        }
        float m0 = leaky(a0 + b0);
        float m1 = leaky(a1 + b1);
        // single-pass LN, 4 interleaved butterfly chains
        float sm0 = m0, qq0 = m0 * m0, sm1 = m1, qq1 = m1 * m1;
#pragma unroll
        for (int d = 16; d; d >>= 1) {
            sm0 += __shfl_xor_sync(0xffffffffu, sm0, d);
            qq0 += __shfl_xor_sync(0xffffffffu, qq0, d);
            sm1 += __shfl_xor_sync(0xffffffffu, sm1, d);
            qq1 += __shfl_xor_sync(0xffffffffu, qq1, d);
        }
        float mu0 = sm0 * (1.f / 32.f), var0 = fmaxf(qq0 * (1.f / 32.f) - mu0 * mu0, 0.f);
        float mu1 = sm1 * (1.f / 32.f), var1 = fmaxf(qq1 * (1.f / 32.f) - mu1 * mu1, 0.f);
        g_e[e0 * 32 + lane] = ev0 + (m0 - mu0) * rsqrtf(var0 + LN_EPS) * sc + bi;
        g_e[e1 * 32 + lane] = ev1 + (m1 - mu1) * rsqrtf(var1 + LN_EPS) * sc + bi;
    }
}

// ================= per-step: node update + fused agg + next-step Hs/Hd (or decoder) ========
__global__ void __launch_bounds__(256) node_update(
        const float* __restrict__ nW, const float* __restrict__ nb,
        const float* __restrict__ lns, const float* __restrict__ lnb,
        const float* __restrict__ eW_next, int last,
        const float* __restrict__ dW1, const float* __restrict__ db1,
        const float* __restrict__ dW2, const float* __restrict__ db2,
        float* __restrict__ out) {
    __shared__ float ws [64 * 32];
    __shared__ float ws2[64 * 32];
    __shared__ float prm[96];
    for (int i = threadIdx.x; i < 2048; i += 256) {
        ws[i] = nW[i];
        ws2[i] = last ? ((i < 1024) ? dW1[i] : 0.f) : eW_next[32 * 32 + i];
    }
    if (threadIdx.x < 32) {
        prm[threadIdx.x] = nb[threadIdx.x];
        prm[32 + threadIdx.x] = lns[threadIdx.x];
        prm[64 + threadIdx.x] = lnb[threadIdx.x];
    }
    __syncthreads();
    int lane = threadIdx.x & 31;
    int warp = (blockIdx.x * blockDim.x + threadIdx.x) >> 5;
    int nwarps = (gridDim.x * blockDim.x) >> 5;
    float bias = prm[lane], sc = prm[32 + lane], bi = prm[64 + lane];

    for (int n = warp; n < N_NODES; n += nwarps) {
        int beg = g_off[n], end = g_off[n + 1];
        float s0 = 0.f, s1 = 0.f, s2 = 0.f, s3 = 0.f;
        int j = beg;
        for (; j + 3 < end; j += 4) {
            s0 += g_e[(j + 0) * 32 + lane];
            s1 += g_e[(j + 1) * 32 + lane];
            s2 += g_e[(j + 2) * 32 + lane];
            s3 += g_e[(j + 3) * 32 + lane];
        }
        for (; j < end; j++) s0 += g_e[j * 32 + lane];
        float av = ((s0 + s1) + (s2 + s3)) * g_inv[n];

        float hv = g_h[n * 32 + lane];
        float acc = bias;
#pragma unroll
        for (int k = 0; k < 32; k++) {
            float a = __shfl_sync(0xffffffffu, hv, k);
            float b2 = __shfl_sync(0xffffffffu, av, k);
            acc += a * ws[k * 32 + lane] + b2 * ws[(32 + k) * 32 + lane];
        }
        float m = leaky(acc);
        float sm = m, qq = m * m;
#pragma unroll
        for (int d = 16; d; d >>= 1) {
            sm += __shfl_xor_sync(0xffffffffu, sm, d);
            qq += __shfl_xor_sync(0xffffffffu, qq, d);
        }
        float mu = sm * (1.f / 32.f);
        float var = fmaxf(qq * (1.f / 32.f) - mu * mu, 0.f);
        float hn = hv + (m - mu) * rsqrtf(var + LN_EPS) * sc + bi;
        g_h[n * 32 + lane] = hn;

        if (!last) {
            float aS = 0.f, aD = 0.f;
#pragma unroll
            for (int k = 0; k < 32; k++) {
                float t = __shfl_sync(0xffffffffu, hn, k);
                aS += t * ws2[k * 32 + lane];
                aD += t * ws2[(32 + k) * 32 + lane];
            }
            g_hs[n * 32 + lane] = aS;
            g_hd[n * 32 + lane] = aD;
        } else {
            float t = db1[lane];
#pragma unroll
            for (int k = 0; k < 32; k++)
                t += __shfl_sync(0xffffffffu, hn, k) * ws2[k * 32 + lane];
            t = leaky(t) * dW2[lane];
#pragma unroll
            for (int d = 16; d; d >>= 1)
                t += __shfl_xor_sync(0xffffffffu, t, d);
            if (lane == 0) out[n] = t + db2[0];
        }
    }
}

// ================= launch =================
extern "C" void kernel_launch(void* const* d_in, const int* in_sizes, int n_in,
                              void* d_out, int out_size) {
    const float* x   = (const float*)d_in[0];
    const float* ea  = (const float*)d_in[1];
    const int*   snd = (const int*)d_in[2];
    const int*   rcv = (const int*)d_in[3];
    const float* neW = (const float*)d_in[4];
    const float* neb = (const float*)d_in[5];
    const float* eeW = (const float*)d_in[6];
    const float* eeb = (const float*)d_in[7];
    const float* eW  = (const float*)d_in[8];
    const float* eb  = (const float*)d_in[9];
    const float* els = (const float*)d_in[10];
    const float* elb = (const float*)d_in[11];
    const float* nW  = (const float*)d_in[12];
    const float* nb  = (const float*)d_in[13];
    const float* nls = (const float*)d_in[14];
    const float* nlb = (const float*)d_in[15];
    const float* dW1 = (const float*)d_in[16];
    const float* db1 = (const float*)d_in[17];
    const float* dW2 = (const float*)d_in[18];
    const float* db2 = (const float*)d_in[19];
    float* out = (float*)d_out;

    hist_edges<<<(N_EDGES + 255) / 256, 256>>>(rcv);                       // 1
    scan_all<<<1, 1024>>>();                                               // 2
    fused_encode<<<ENC_EDGE_BLOCKS + ENC_NODE_BLOCKS, 256>>>(              // 3
        ea, snd, rcv, eeW, eeb, x, neW, neb, eW);

    for (int s = 0; s < STEPS; s++) {
        edge_update<<<EDGE_BLOCKS, 256>>>(eW + s * 96 * 32, eb + s * 32,   // 4 (profiled), 6, 8, ...
                                          els + s * 32, elb + s * 32);
        int last = (s == STEPS - 1);
        node_update<<<NODE_BLOCKS, 256>>>(nW + s * 64 * 32, nb + s * 32,
                                          nls + s * 32, nlb + s * 32,
                                          eW + (s + 1 < STEPS ? (s + 1) * 96 * 32 : 0), last,
                                          dW1, db1, dW2, db2, out);
    }
}

// round 5
// speedup vs baseline: 1.6626x; 1.0178x over previous
#include <cuda_runtime.h>
#include <cuda_bf16.h>

#define N_NODES 50000
#define N_EDGES 800000
#define STEPS 10
#define NEG_SLOPE 0.01f
#define LN_EPS 1e-5f

#define ENC_EDGE_BLOCKS 3125              // 3125*256 = 800000
#define ENC_NODE_BLOCKS 1184
#define EDGE_BLOCKS 592                   // 4 blocks/SM * 148
#define NODE_BLOCKS 592

// ---------------- device scratch (no allocation allowed) ----------------
__device__ float g_h [N_NODES * 32];
__device__ float g_e [N_EDGES * 32];      // receiver-sorted
__device__ float g_hs[N_NODES * 32];
__device__ float g_hd[N_NODES * 32];
__device__ float g_inv[N_NODES];
__device__ int   g_hist[N_NODES];         // zero-init; re-zeroed inside fused_encode each replay
__device__ int   g_off [N_NODES + 1];
__device__ int   g_cursor[N_NODES];
__device__ int   g_snd_s[N_EDGES];
__device__ int   g_rcv_s[N_EDGES];

__device__ __forceinline__ float leaky(float v) {
    return v >= 0.f ? v : NEG_SLOPE * v;
}

// ================= launch 1: in-degree histogram =================
__global__ void hist_edges(const int* __restrict__ rcv) {
    int i = blockIdx.x * blockDim.x + threadIdx.x;
    if (i < N_EDGES) atomicAdd(&g_hist[rcv[i]], 1);
}

// ================= launch 2: single-block full scan -> off/cursor/inv =================
__global__ void scan_all() {
    __shared__ int sh[1024];
    int tid = threadIdx.x;
    int base = 0;
    const int nchunks = (N_NODES + 1023) / 1024;
    for (int c = 0; c < nchunks; c++) {
        __syncthreads();
        int i = c * 1024 + tid;
        int v = (i < N_NODES) ? g_hist[i] : 0;
        sh[tid] = v;
        __syncthreads();
#pragma unroll
        for (int d = 1; d < 1024; d <<= 1) {
            int t = (tid >= d) ? sh[tid - d] : 0;
            __syncthreads();
            sh[tid] += t;
            __syncthreads();
        }
        if (i < N_NODES) {
            int off = base + sh[tid] - v;
            g_off[i] = off;
            g_cursor[i] = off;
            g_inv[i] = 1.f / fmaxf((float)v, 1.f);
        }
        base += sh[1023];
    }
    if (tid == 0) g_off[N_NODES] = base;   // == N_EDGES
}

// ================= launch 3: fused scatter + encoders + node_pre(step0) =================
__global__ void __launch_bounds__(256) fused_encode(
        const float* __restrict__ ea, const int* __restrict__ snd, const int* __restrict__ rcv,
        const float* __restrict__ eeW, const float* __restrict__ eeb,
        const float* __restrict__ x, const float* __restrict__ neW, const float* __restrict__ neb,
        const float* __restrict__ eW0) {
    __shared__ float sw[64 * 32];
    __shared__ float sw2[224];

    if (blockIdx.x < ENC_EDGE_BLOCKS) {
        if (threadIdx.x < 96) sw[threadIdx.x] = eeW[threadIdx.x];
        else if (threadIdx.x < 128) sw[threadIdx.x] = eeb[threadIdx.x - 96];
        __syncthreads();
        int i = blockIdx.x * 256 + threadIdx.x;
        if (i < N_EDGES) {
            int r = rcv[i], s = snd[i];
            int pos = atomicAdd(&g_cursor[r], 1);
            g_snd_s[pos] = s;
            g_rcv_s[pos] = r;
            float a0 = ea[i * 3 + 0], a1 = ea[i * 3 + 1], a2 = ea[i * 3 + 2];
            float4* dst = (float4*)&g_e[pos * 32];
#pragma unroll
            for (int c4 = 0; c4 < 8; c4++) {
                float4 v;
                v.x = leaky(sw[96 + c4 * 4 + 0] + a0 * sw[0 * 32 + c4 * 4 + 0] + a1 * sw[1 * 32 + c4 * 4 + 0] + a2 * sw[2 * 32 + c4 * 4 + 0]);
                v.y = leaky(sw[96 + c4 * 4 + 1] + a0 * sw[0 * 32 + c4 * 4 + 1] + a1 * sw[1 * 32 + c4 * 4 + 1] + a2 * sw[2 * 32 + c4 * 4 + 1]);
                v.z = leaky(sw[96 + c4 * 4 + 2] + a0 * sw[0 * 32 + c4 * 4 + 2] + a1 * sw[1 * 32 + c4 * 4 + 2] + a2 * sw[2 * 32 + c4 * 4 + 2]);
                v.w = leaky(sw[96 + c4 * 4 + 3] + a0 * sw[0 * 32 + c4 * 4 + 3] + a1 * sw[1 * 32 + c4 * 4 + 3] + a2 * sw[2 * 32 + c4 * 4 + 3]);
                dst[c4] = v;
            }
        }
    } else {
        for (int i = threadIdx.x; i < 2048; i += 256) sw[i] = eW0[32 * 32 + i];
        for (int i = threadIdx.x; i < 224; i += 256)
            sw2[i] = (i < 192) ? neW[i] : neb[i - 192];
        __syncthreads();
        int lane = threadIdx.x & 31;
        int nb = blockIdx.x - ENC_EDGE_BLOCKS;
        int warp = nb * 8 + (threadIdx.x >> 5);
        int nwarps = ENC_NODE_BLOCKS * 8;
        for (int n = warp; n < N_NODES; n += nwarps) {
            float a = sw2[192 + lane];
#pragma unroll
            for (int k = 0; k < 6; k++) a += x[n * 6 + k] * sw2[k * 32 + lane];
            float hv = leaky(a);
            g_h[n * 32 + lane] = hv;
            float aS = 0.f, aD = 0.f;
#pragma unroll
            for (int k = 0; k < 32; k++) {
                float t = __shfl_sync(0xffffffffu, hv, k);
                aS += t * sw[k * 32 + lane];
                aD += t * sw[(32 + k) * 32 + lane];
            }
            g_hs[n * 32 + lane] = aS;
            g_hd[n * 32 + lane] = aD;
        }
        int gtid = nb * 256 + threadIdx.x;
        for (int i = gtid; i < N_NODES; i += ENC_NODE_BLOCKS * 256) g_hist[i] = 0;
    }
}

// ================= per-step: edge update (reg-W, uniform-LDG broadcast GEMV) =================
__global__ void __launch_bounds__(256, 4) edge_update(
        const float* __restrict__ eW, const float* __restrict__ eb,
        const float* __restrict__ lns, const float* __restrict__ lnb) {
    int lane = threadIdx.x & 31;
    int warp = (blockIdx.x * blockDim.x + threadIdx.x) >> 5;
    int nwarps = (gridDim.x * blockDim.x) >> 5;

    // lane holds column `lane` of W_e (rows 0..31 of eW)
    float w[32];
#pragma unroll
    for (int k = 0; k < 32; k++) w[k] = eW[k * 32 + lane];
    float bias = eb[lane], sc = lns[lane], bi = lnb[lane];

    const int npairs = N_EDGES / 2;
    for (int p = warp; p < npairs; p += nwarps) {
        int e0 = 2 * p, e1 = 2 * p + 1;
        int2 ss = *(const int2*)&g_snd_s[e0];
        int2 rr = *(const int2*)&g_rcv_s[e0];
        float ev0 = g_e[e0 * 32 + lane];   // brings both rows into L1
        float ev1 = g_e[e1 * 32 + lane];
        float a0 = bias + g_hs[ss.x * 32 + lane] + g_hd[rr.x * 32 + lane];
        float a1 = bias + g_hs[ss.y * 32 + lane] + g_hd[rr.y * 32 + lane];
        float b0 = 0.f, b1 = 0.f;
#pragma unroll
        for (int k4 = 0; k4 < 8; k4++) {
            // uniform address -> broadcast wavefront, 4 features per MIO op, L1-hit
            float4 u0 = *(const float4*)&g_e[e0 * 32 + k4 * 4];
            float4 u1 = *(const float4*)&g_e[e1 * 32 + k4 * 4];
            a0 += u0.x * w[k4 * 4 + 0];  b0 += u0.y * w[k4 * 4 + 1];
            a0 += u0.z * w[k4 * 4 + 2];  b0 += u0.w * w[k4 * 4 + 3];
            a1 += u1.x * w[k4 * 4 + 0];  b1 += u1.y * w[k4 * 4 + 1];
            a1 += u1.z * w[k4 * 4 + 2];  b1 += u1.w * w[k4 * 4 + 3];
        }
        float m0 = leaky(a0 + b0);
        float m1 = leaky(a1 + b1);
        float sm0 = m0, qq0 = m0 * m0, sm1 = m1, qq1 = m1 * m1;
#pragma unroll
        for (int d = 16; d; d >>= 1) {
            sm0 += __shfl_xor_sync(0xffffffffu, sm0, d);
            qq0 += __shfl_xor_sync(0xffffffffu, qq0, d);
            sm1 += __shfl_xor_sync(0xffffffffu, sm1, d);
            qq1 += __shfl_xor_sync(0xffffffffu, qq1, d);
        }
        float mu0 = sm0 * (1.f / 32.f), var0 = fmaxf(qq0 * (1.f / 32.f) - mu0 * mu0, 0.f);
        float mu1 = sm1 * (1.f / 32.f), var1 = fmaxf(qq1 * (1.f / 32.f) - mu1 * mu1, 0.f);
        g_e[e0 * 32 + lane] = ev0 + (m0 - mu0) * rsqrtf(var0 + LN_EPS) * sc + bi;
        g_e[e1 * 32 + lane] = ev1 + (m1 - mu1) * rsqrtf(var1 + LN_EPS) * sc + bi;
    }
}

// ================= per-step: node update (transposed-W smem, broadcast reads) =================
// wsT / ws2T padded row stride 68 floats -> conflict-free LDS.128 per quarter-warp
__global__ void __launch_bounds__(256) node_update(
        const float* __restrict__ nW, const float* __restrict__ nb,
        const float* __restrict__ lns, const float* __restrict__ lnb,
        const float* __restrict__ eW_next, int last,
        const float* __restrict__ dW1, const float* __restrict__ db1,
        const float* __restrict__ dW2, const float* __restrict__ db2,
        float* __restrict__ out) {
    __shared__ float wsT [32 * 68];   // node W transposed: wsT[c*68 + k], k in [0,64)
    __shared__ float ws2T[32 * 68];   // next-step eW rows 32..95 transposed (or dec_W1, k in [0,32))
    __shared__ float sv  [8 * 64];    // per-warp staging: [0:32) av, [32:64) hn
    __shared__ float prm [96];

    for (int i = threadIdx.x; i < 2048; i += 256) {
        int k = i >> 5, c = i & 31;
        wsT[c * 68 + k] = nW[i];
        if (last) { if (i < 1024) ws2T[c * 68 + k] = dW1[i]; }
        else        ws2T[c * 68 + k] = eW_next[32 * 32 + i];
    }
    if (threadIdx.x < 32) {
        prm[threadIdx.x]      = nb[threadIdx.x];
        prm[32 + threadIdx.x] = lns[threadIdx.x];
        prm[64 + threadIdx.x] = lnb[threadIdx.x];
    }
    __syncthreads();
    int lane = threadIdx.x & 31;
    int wslot = (threadIdx.x >> 5) * 64;
    int warp = (blockIdx.x * blockDim.x + threadIdx.x) >> 5;
    int nwarps = (gridDim.x * blockDim.x) >> 5;
    float bias = prm[lane], sc = prm[32 + lane], bi = prm[64 + lane];

    for (int n = warp; n < N_NODES; n += nwarps) {
        int beg = g_off[n], end = g_off[n + 1];
        float s0 = 0.f, s1 = 0.f, s2 = 0.f, s3 = 0.f;
        int j = beg;
        for (; j + 3 < end; j += 4) {
            s0 += g_e[(j + 0) * 32 + lane];
            s1 += g_e[(j + 1) * 32 + lane];
            s2 += g_e[(j + 2) * 32 + lane];
            s3 += g_e[(j + 3) * 32 + lane];
        }
        for (; j < end; j++) s0 += g_e[j * 32 + lane];
        float av = ((s0 + s1) + (s2 + s3)) * g_inv[n];
        float hv = g_h[n * 32 + lane];      // brings row into L1
        sv[wslot + lane] = av;
        __syncwarp();

        float acc = bias, acb = 0.f;
#pragma unroll
        for (int k4 = 0; k4 < 8; k4++) {
            float4 hb = *(const float4*)&g_h[n * 32 + k4 * 4];   // uniform broadcast, L1-hit
            float4 ab = *(const float4*)&sv[wslot + k4 * 4];     // broadcast LDS.128
            const float* wr = &wsT[lane * 68 + k4 * 4];
            float4 w1 = *(const float4*)wr;                      // W rows k..k+3
            float4 w2 = *(const float4*)(wr + 32);               // W rows 32+k..
            acc += hb.x * w1.x + ab.x * w2.x;
            acb += hb.y * w1.y + ab.y * w2.y;
            acc += hb.z * w1.z + ab.z * w2.z;
            acb += hb.w * w1.w + ab.w * w2.w;
        }
        float m = leaky(acc + acb);
        float sm = m, qq = m * m;
#pragma unroll
        for (int d = 16; d; d >>= 1) {
            sm += __shfl_xor_sync(0xffffffffu, sm, d);
            qq += __shfl_xor_sync(0xffffffffu, qq, d);
        }
        float mu = sm * (1.f / 32.f);
        float var = fmaxf(qq * (1.f / 32.f) - mu * mu, 0.f);
        float hn = hv + (m - mu) * rsqrtf(var + LN_EPS) * sc + bi;
        g_h[n * 32 + lane] = hn;
        sv[wslot + 32 + lane] = hn;
        __syncwarp();

        if (!last) {
            float aS = 0.f, aD = 0.f;
#pragma unroll
            for (int k4 = 0; k4 < 8; k4++) {
                float4 hb = *(const float4*)&sv[wslot + 32 + k4 * 4];
                const float* wr = &ws2T[lane * 68 + k4 * 4];
                float4 w1 = *(const float4*)wr;        // eW rows 32+k (src part)
                float4 w2 = *(const float4*)(wr + 32); // eW rows 64+k (dst part)
                aS += hb.x * w1.x; aD += hb.x * w2.x;
                aS += hb.y * w1.y; aD += hb.y * w2.y;
                aS += hb.z * w1.z; aD += hb.z * w2.z;
                aS += hb.w * w1.w; aD += hb.w * w2.w;
            }
            g_hs[n * 32 + lane] = aS;
            g_hd[n * 32 + lane] = aD;
        } else {
            float t = db1[lane];
#pragma unroll
            for (int k4 = 0; k4 < 8; k4++) {
                float4 hb = *(const float4*)&sv[wslot + 32 + k4 * 4];
                float4 w1 = *(const float4*)&ws2T[lane * 68 + k4 * 4];
                t += hb.x * w1.x + hb.y * w1.y + hb.z * w1.z + hb.w * w1.w;
            }
            t = leaky(t) * dW2[lane];
#pragma unroll
            for (int d = 16; d; d >>= 1)
                t += __shfl_xor_sync(0xffffffffu, t, d);
            if (lane == 0) out[n] = t + db2[0];
        }
        __syncwarp();
    }
}

// ================= launch =================
extern "C" void kernel_launch(void* const* d_in, const int* in_sizes, int n_in,
                              void* d_out, int out_size) {
    const float* x   = (const float*)d_in[0];
    const float* ea  = (const float*)d_in[1];
    const int*   snd = (const int*)d_in[2];
    const int*   rcv = (const int*)d_in[3];
    const float* neW = (const float*)d_in[4];
    const float* neb = (const float*)d_in[5];
    const float* eeW = (const float*)d_in[6];
    const float* eeb = (const float*)d_in[7];
    const float* eW  = (const float*)d_in[8];
    const float* eb  = (const float*)d_in[9];
    const float* els = (const float*)d_in[10];
    const float* elb = (const float*)d_in[11];
    const float* nW  = (const float*)d_in[12];
    const float* nb  = (const float*)d_in[13];
    const float* nls = (const float*)d_in[14];
    const float* nlb = (const float*)d_in[15];
    const float* dW1 = (const float*)d_in[16];
    const float* db1 = (const float*)d_in[17];
    const float* dW2 = (const float*)d_in[18];
    const float* db2 = (const float*)d_in[19];
    float* out = (float*)d_out;

    hist_edges<<<(N_EDGES + 255) / 256, 256>>>(rcv);
    scan_all<<<1, 1024>>>();
    fused_encode<<<ENC_EDGE_BLOCKS + ENC_NODE_BLOCKS, 256>>>(
        ea, snd, rcv, eeW, eeb, x, neW, neb, eW);

    for (int s = 0; s < STEPS; s++) {
        edge_update<<<EDGE_BLOCKS, 256>>>(eW + s * 96 * 32, eb + s * 32,
                                          els + s * 32, elb + s * 32);
        int last = (s == STEPS - 1);
        node_update<<<NODE_BLOCKS, 256>>>(nW + s * 64 * 32, nb + s * 32,
                                          nls + s * 32, nlb + s * 32,
                                          eW + (s + 1 < STEPS ? (s + 1) * 96 * 32 : 0), last,
                                          dW1, db1, dW2, db2, out);
    }
}